// round 5
// baseline (speedup 1.0000x reference)
#include <cuda_runtime.h>
#include <math.h>

// Problem constants
constexpr int LN = 256;    // utterances
constexpr int DN = 300;    // embedding dim
constexpr int SN = 16;     // concepts per utterance
constexpr int KN = 16;     // dst per concept
constexpr int EN = 2048;   // edges
constexpr int CN = 7;      // classes
constexpr float NEGV = -1000000000.0f;

// Scratch (device globals, no allocation)
__device__ float g_hidden[LN * DN];
__device__ float g_P0[LN * DN];   // utt @ W_basis[0]
__device__ float g_P1[LN * DN];   // utt @ W_basis[1]
__device__ float g_Q[LN * DN];
__device__ float g_K[LN * DN];
__device__ float g_V[LN * DN];
__device__ float g_ctx[LN * DN];
__device__ float g_relatt[LN * DN];
__device__ float g_nodes[(long)LN * 48 * DN]; // 14.7 MB
__device__ float g_score[LN * 48];
__device__ int   g_nmask[LN * 48];
__device__ float g_feat[LN * 900];
__device__ float g_fuse[LN * DN];

// ---------------------------------------------------------------------------
// Tiled SGEMM: O[32x64 tile] = A[256 x Kdim] @ W[Kdim x 300] (+bias, opt relu)
// 512 threads, 1x4 micro-tile (row = t>>4, cols = (t&15)*4 ..+3).
// Double-buffered K chunks of 32 with register prefetch.
__device__ __forceinline__ void gemm_core(
    const float* __restrict__ A, const float* __restrict__ W,
    const float* __restrict__ bias, float* __restrict__ O,
    int Kdim, bool relu)
{
    __shared__ float As[2][32][33];
    __shared__ __align__(16) float Ws[2][32][64];
    int t = threadIdx.x;               // 0..511
    int m0 = blockIdx.y * 32, n0 = blockIdx.x * 64;
    int row = t >> 4;                  // 0..31
    int col0 = (t & 15) * 4;           // 0..60
    int ar0 = t >> 5, ac = t & 31;     // A loader: rows ar0, ar0+16, col ac
    int wr0 = t >> 6, wc = t & 63;     // W loader: rows wr0+8i, col wc
    float acc0 = 0.f, acc1 = 0.f, acc2 = 0.f, acc3 = 0.f;
    int nchunks = (Kdim + 31) >> 5;

    float a_reg[2], w_reg[4];
    a_reg[0] = (ac < Kdim) ? A[(m0 + ar0) * Kdim + ac] : 0.f;
    a_reg[1] = (ac < Kdim) ? A[(m0 + ar0 + 16) * Kdim + ac] : 0.f;
#pragma unroll
    for (int i = 0; i < 4; i++) {
        int kk = wr0 + i * 8, nn = n0 + wc;
        w_reg[i] = (kk < Kdim && nn < DN) ? W[kk * DN + nn] : 0.f;
    }
    As[0][ar0][ac] = a_reg[0];
    As[0][ar0 + 16][ac] = a_reg[1];
#pragma unroll
    for (int i = 0; i < 4; i++) Ws[0][wr0 + i * 8][wc] = w_reg[i];
    __syncthreads();

    for (int c = 1; c < nchunks; c++) {
        int k0 = c << 5;
        // prefetch chunk c into registers (overlaps compute on chunk c-1)
        {
            int kk = k0 + ac;
            a_reg[0] = (kk < Kdim) ? A[(m0 + ar0) * Kdim + kk] : 0.f;
            a_reg[1] = (kk < Kdim) ? A[(m0 + ar0 + 16) * Kdim + kk] : 0.f;
        }
#pragma unroll
        for (int i = 0; i < 4; i++) {
            int kk = k0 + wr0 + i * 8, nn = n0 + wc;
            w_reg[i] = (kk < Kdim && nn < DN) ? W[kk * DN + nn] : 0.f;
        }
        int cur = (c - 1) & 1;
#pragma unroll
        for (int k = 0; k < 32; k++) {
            float4 w4 = *(const float4*)&Ws[cur][k][col0];
            float a = As[cur][row][k];
            acc0 += a * w4.x; acc1 += a * w4.y;
            acc2 += a * w4.z; acc3 += a * w4.w;
        }
        __syncthreads();
        int nxt = c & 1;
        As[nxt][ar0][ac] = a_reg[0];
        As[nxt][ar0 + 16][ac] = a_reg[1];
#pragma unroll
        for (int i = 0; i < 4; i++) Ws[nxt][wr0 + i * 8][wc] = w_reg[i];
        __syncthreads();
    }
    int cur = (nchunks - 1) & 1;
#pragma unroll
    for (int k = 0; k < 32; k++) {
        float4 w4 = *(const float4*)&Ws[cur][k][col0];
        float a = As[cur][row][k];
        acc0 += a * w4.x; acc1 += a * w4.y;
        acc2 += a * w4.z; acc3 += a * w4.w;
    }

    int m = m0 + row;
    float b0 = 0.f, b1 = 0.f, b2 = 0.f, b3 = 0.f;
    if (bias) {
        if (col0 + 0 < DN) b0 = bias[col0 + n0 + 0] - 0.f;
        // (loaded individually below to keep guards simple)
    }
    float vv[4] = { acc0, acc1, acc2, acc3 };
#pragma unroll
    for (int j = 0; j < 4; j++) {
        int n = n0 + col0 + j;
        if (n < DN) {
            float v = vv[j] + (bias ? bias[n] : 0.f);
            O[m * DN + n] = relu ? fmaxf(v, 0.f) : v;
        }
    }
    (void)b0; (void)b1; (void)b2; (void)b3;
}

// Batched: z selects which of 6 projections of utt we compute.
__global__ void __launch_bounds__(512) gemm6_kernel(
    const float* __restrict__ utt,
    const float* __restrict__ Wself, const float* __restrict__ brg,
    const float* __restrict__ Wb,
    const float* __restrict__ Wq, const float* __restrict__ Wk2,
    const float* __restrict__ Wv)
{
    int z = blockIdx.z;
    const float* Wz;
    float* Oz;
    const float* bz = nullptr;
    switch (z) {
        case 0: Wz = Wself; Oz = g_hidden; bz = brg; break;
        case 1: Wz = Wb;            Oz = g_P0; break;
        case 2: Wz = Wb + DN * DN;  Oz = g_P1; break;
        case 3: Wz = Wq;  Oz = g_Q; break;
        case 4: Wz = Wk2; Oz = g_K; break;
        default: Wz = Wv; Oz = g_V; break;
    }
    gemm_core(utt, Wz, bz, Oz, DN, false);
}

// relatt = ctx @ Wo
__global__ void __launch_bounds__(512) gemmWo_kernel(const float* __restrict__ Wo)
{
    gemm_core(g_ctx, Wo, nullptr, g_relatt, DN, false);
}

// fuse = relu(feat @ Wfuse + bfuse)   (K = 900)
__global__ void __launch_bounds__(512) gemmFuse_kernel(
    const float* __restrict__ Wf, const float* __restrict__ bf)
{
    gemm_core(g_feat, Wf, bf, g_fuse, 900, true);
}

// ---------------------------------------------------------------------------
// RGCN edge scatter: hidden[dst] += comp[et,0]*P0[src] + comp[et,1]*P1[src]
__global__ void __launch_bounds__(128) scatter_kernel(
    const int* __restrict__ src, const int* __restrict__ dst,
    const int* __restrict__ et, const float* __restrict__ comp)
{
    int e = blockIdx.x;
    int sl = src[e], dl = dst[e], r = et[e];
    float c0 = comp[2 * r], c1 = comp[2 * r + 1];
    const float* p0 = g_P0 + (long)sl * DN;
    const float* p1 = g_P1 + (long)sl * DN;
    float* h = g_hidden + (long)dl * DN;
    for (int d = threadIdx.x; d < DN; d += blockDim.x)
        atomicAdd(h + d, c0 * p0[d] + c1 * p1[d]);
}

// ---------------------------------------------------------------------------
// Windowed attention context (only center q needed): ctx[l] = sum_j a[h,j]*V[win_j]
__global__ void __launch_bounds__(128) attn_ctx_kernel() {
    int l = blockIdx.x;
    int tid = threadIdx.x, warp = tid >> 5, lane = tid & 31;
    __shared__ float qsm[DN];
    __shared__ float lg[2][3];
    int w[3];
    w[0] = l > 0 ? l - 1 : 0;
    w[1] = l;
    w[2] = l < LN - 1 ? l + 1 : LN - 1;
    for (int d = tid; d < DN; d += blockDim.x) qsm[d] = g_Q[l * DN + d];
    __syncthreads();
    for (int p = warp; p < 6; p += 4) {
        int h = p / 3, j = p - 3 * h;
        const float* kr = g_K + (long)w[j] * DN + h * 150;
        const float* qh = qsm + h * 150;
        float acc = 0.f;
        for (int d = lane; d < 150; d += 32) acc += qh[d] * kr[d];
        for (int off = 16; off; off >>= 1) acc += __shfl_down_sync(0xffffffffu, acc, off);
        if (lane == 0) lg[h][j] = acc * 0.081649658092772603f;  // 1/sqrt(150)
    }
    __syncthreads();
    float a[2][3];
#pragma unroll
    for (int h = 0; h < 2; h++) {
        float m = fmaxf(lg[h][0], fmaxf(lg[h][1], lg[h][2]));
        float s = 0.f;
#pragma unroll
        for (int j = 0; j < 3; j++) { a[h][j] = expf(lg[h][j] - m); s += a[h][j]; }
        float inv = 1.f / s;
#pragma unroll
        for (int j = 0; j < 3; j++) a[h][j] *= inv;
    }
    for (int d = tid; d < DN; d += blockDim.x) {
        int h = d >= 150;
        float c = a[h][0] * g_V[(long)w[0] * DN + d]
                + a[h][1] * g_V[(long)w[1] * DN + d]
                + a[h][2] * g_V[(long)w[2] * DN + d];
        g_ctx[l * DN + d] = c;
    }
}

// ---------------------------------------------------------------------------
// Concept two-level attention. One block per (n,l,s), 256 threads (8 warps).
// Gathered rows cached in SMEM (float4) and read from global exactly once.
// Vectorized LDS (float4) + precomputed src*r cut instruction count ~2x.
__global__ void __launch_bounds__(256) concept_kernel(
    const int* __restrict__ src_ids, const int* __restrict__ dst_ids,
    const float* __restrict__ wgt, const float* __restrict__ sen,
    const float* __restrict__ table, const float* __restrict__ rvecs)
{
    int s = blockIdx.x, l = blockIdx.y, n = blockIdx.z;
    int tid = threadIdx.x, warp = tid >> 5, lane = tid & 31;
    __shared__ __align__(16) float4 dstc4[KN][75];
    __shared__ __align__(16) float4 srcsm4[75], rsm4[75], relsm4[75], sr4[75];
    __shared__ float d_du[KN], d_nn[KN], d_dp[KN];
    __shared__ int d_val[KN];
    __shared__ float red[8];
    __shared__ float s_nrm;

    int sidx = (n * LN + l) * SN + s;
    int src_id = src_ids[sidx];
    const float4* srow4 = (const float4*)(table + (long)(src_id < 0 ? 0 : src_id) * DN);
    const float4* rel4 = (const float4*)(g_relatt + (long)l * DN);
    const float4* rv4 = (const float4*)(rvecs + (long)n * DN);
    if (tid == 0) s_nrm = 0.f;
    __syncthreads();
    if (tid < 75) {
        float4 v = rel4[tid];
        relsm4[tid] = v;
        atomicAdd(&s_nrm, v.x * v.x + v.y * v.y + v.z * v.z + v.w * v.w);
    } else if (tid < 150) {
        rsm4[tid - 75] = rv4[tid - 75];
    } else if (tid < 225) {
        srcsm4[tid - 150] = srow4[tid - 150];
    }
    __syncthreads();
    if (tid < 75) {
        float4 sv = srcsm4[tid], rv = rsm4[tid];
        sr4[tid] = make_float4(sv.x * rv.x, sv.y * rv.y, sv.z * rv.z, sv.w * rv.w);
    }
    __syncthreads();

    long base = (long)sidx * KN;
#pragma unroll
    for (int kk = 0; kk < 2; kk++) {
        int k = warp + kk * 8;
        int id = dst_ids[base + k];
        const float4* rowv = (const float4*)(table + (long)(id < 0 ? 0 : id) * DN);
        float du = 0.f, nn = 0.f, dp = 0.f;
        for (int i = lane; i < 75; i += 32) {
            float4 v = rowv[i];
            dstc4[k][i] = v;
            float4 rl = relsm4[i];
            float4 sv = sr4[i];
            du += rl.x * v.x + rl.y * v.y + rl.z * v.z + rl.w * v.w;
            nn += v.x * v.x + v.y * v.y + v.z * v.z + v.w * v.w;
            dp += sv.x * v.x + sv.y * v.y + sv.z * v.z + sv.w * v.w;
        }
        for (int off = 16; off; off >>= 1) {
            du += __shfl_down_sync(0xffffffffu, du, off);
            nn += __shfl_down_sync(0xffffffffu, nn, off);
            dp += __shfl_down_sync(0xffffffffu, dp, off);
        }
        if (lane == 0) { d_du[k] = du; d_nn[k] = nn; d_dp[k] = dp; d_val[k] = (id >= 0); }
    }
    __syncthreads();

    // Tiny softmaxes, redundantly per active thread (only tid<75 need them).
    float ssc = 0.f;
    if (tid < 75) {
        float rn = sqrtf(s_nrm);
        float a1[KN], w2[KN];
        {
            float om[KN];
            float mx = NEGV;
#pragma unroll
            for (int k = 0; k < KN; k++) {
                if (d_val[k]) {
                    float cosv = fabsf(d_du[k]) / (rn * sqrtf(d_nn[k]) + 1e-8f);
                    om[k] = 0.5f * wgt[base + k] * cosv + 0.5f * fabsf(sen[base + k]);
                } else om[k] = NEGV;
                mx = fmaxf(mx, om[k]);
            }
            float sum = 0.f;
#pragma unroll
            for (int k = 0; k < KN; k++) { a1[k] = expf(om[k] - mx); sum += a1[k]; }
            float inv = 1.f / sum;
#pragma unroll
            for (int k = 0; k < KN; k++) a1[k] = a1[k] * inv * (d_val[k] ? 1.f : 0.f);

            float sk[KN], a2[KN];
            mx = NEGV;
#pragma unroll
            for (int k = 0; k < KN; k++) {
                sk[k] = d_val[k] ? a1[k] * d_dp[k] : NEGV;
                mx = fmaxf(mx, sk[k]);
            }
            sum = 0.f;
#pragma unroll
            for (int k = 0; k < KN; k++) { a2[k] = expf(sk[k] - mx); sum += a2[k]; }
            inv = 1.f / sum;
#pragma unroll
            for (int k = 0; k < KN; k++) w2[k] = a2[k] * inv * (d_val[k] ? 1.f : 0.f) * a1[k];
        }

        // src2 (float4) and its score against relatt
        float4 a = make_float4(0.f, 0.f, 0.f, 0.f);
#pragma unroll
        for (int k = 0; k < KN; k++) {
            float4 dv = dstc4[k][tid];
            a.x += w2[k] * dv.x; a.y += w2[k] * dv.y;
            a.z += w2[k] * dv.z; a.w += w2[k] * dv.w;
        }
        float4 sv = srcsm4[tid];
        float4 rv = rsm4[tid];
        float4 v;
        v.x = sv.x + rv.x * a.x; v.y = sv.y + rv.y * a.y;
        v.z = sv.z + rv.z * a.z; v.w = sv.w + rv.w * a.w;
        long nbase = ((long)l * 48 + n * SN + s) * 75;
        ((float4*)g_nodes)[nbase + tid] = v;
        float4 rl = relsm4[tid];
        ssc = rl.x * v.x + rl.y * v.y + rl.z * v.z + rl.w * v.w;
    }
    for (int off = 16; off; off >>= 1) ssc += __shfl_down_sync(0xffffffffu, ssc, off);
    if (lane == 0) red[warp] = ssc;
    __syncthreads();
    if (tid == 0) {
        g_score[l * 48 + n * SN + s] = red[0] + red[1] + red[2];
        g_nmask[l * 48 + n * SN + s] = (src_id >= 0);
    }
}

// ---------------------------------------------------------------------------
// Node-level attention -> sym; assemble feat = [hidden | relatt | sym] (float4)
__global__ void __launch_bounds__(128) symfeat_kernel() {
    int l = blockIdx.x;
    int tid = threadIdx.x;
    __shared__ float att[48];
    __shared__ float scs[48];
    __shared__ int msk[48];
    __shared__ float anyf;
    if (tid < 48) {
        msk[tid] = g_nmask[l * 48 + tid];
        scs[tid] = g_score[l * 48 + tid];
    }
    __syncthreads();
    if (tid == 0) {
        float v[48];
        float mx = NEGV;
        int any = 0;
        for (int j = 0; j < 48; j++) {
            v[j] = msk[j] ? scs[j] : NEGV;
            mx = fmaxf(mx, v[j]);
            any |= msk[j];
        }
        float sum = 0.f;
        for (int j = 0; j < 48; j++) { v[j] = expf(v[j] - mx); sum += v[j]; }
        float inv = 1.f / sum;
        for (int j = 0; j < 48; j++) att[j] = v[j] * inv * (msk[j] ? 1.f : 0.f);
        anyf = any ? 1.f : 0.f;
    }
    __syncthreads();
    if (tid < 75) {
        const float4* nodes4 = (const float4*)g_nodes;
        float4 acc = make_float4(0.f, 0.f, 0.f, 0.f);
#pragma unroll 8
        for (int j = 0; j < 48; j++) {
            float4 v = nodes4[((long)l * 48 + j) * 75 + tid];
            float a = att[j];
            acc.x += a * v.x; acc.y += a * v.y; acc.z += a * v.z; acc.w += a * v.w;
        }
        float an = anyf;
        acc.x *= an; acc.y *= an; acc.z *= an; acc.w *= an;
        float4* feat4 = (float4*)g_feat;
        const float4* hid4 = (const float4*)g_hidden;
        const float4* rel4 = (const float4*)g_relatt;
        feat4[(long)l * 225 + tid] = hid4[(long)l * 75 + tid];
        feat4[(long)l * 225 + 75 + tid] = rel4[(long)l * 75 + tid];
        feat4[(long)l * 225 + 150 + tid] = acc;
    }
}

// ---------------------------------------------------------------------------
// head: out[l] = log_softmax(fuse[l] @ W_out + b_out). One warp per row.
__global__ void __launch_bounds__(256) head_kernel(
    const float* __restrict__ Wo2, const float* __restrict__ bo,
    float* __restrict__ out)
{
    int l = blockIdx.x * 8 + (threadIdx.x >> 5);
    int lane = threadIdx.x & 31;
    float acc[CN];
#pragma unroll
    for (int c = 0; c < CN; c++) acc[c] = 0.f;
    const float* hrow = g_fuse + (long)l * DN;
    for (int i = lane; i < DN; i += 32) {
        float h = hrow[i];
#pragma unroll
        for (int c = 0; c < CN; c++) acc[c] += h * Wo2[i * CN + c];
    }
#pragma unroll
    for (int c = 0; c < CN; c++)
        for (int off = 16; off; off >>= 1)
            acc[c] += __shfl_down_sync(0xffffffffu, acc[c], off);
    if (lane == 0) {
        float lg[CN];
        float mx = NEGV;
#pragma unroll
        for (int c = 0; c < CN; c++) { lg[c] = acc[c] + bo[c]; mx = fmaxf(mx, lg[c]); }
        float sum = 0.f;
#pragma unroll
        for (int c = 0; c < CN; c++) sum += expf(lg[c] - mx);
        float ls = logf(sum) + mx;
#pragma unroll
        for (int c = 0; c < CN; c++) out[l * CN + c] = lg[c] - ls;
    }
}

// ---------------------------------------------------------------------------
extern "C" void kernel_launch(void* const* d_in, const int* in_sizes, int n_in,
                              void* d_out, int out_size)
{
    const float* utt   = (const float*)d_in[0];
    const int*   ssrc  = (const int*)d_in[1];
    const int*   sdst  = (const int*)d_in[2];
    const int*   setyp = (const int*)d_in[3];
    const int*   csrc  = (const int*)d_in[4];
    const int*   cdst  = (const int*)d_in[5];
    const float* cwgt  = (const float*)d_in[6];
    const float* csen  = (const float*)d_in[7];
    const float* table = (const float*)d_in[8];
    const float* Wb    = (const float*)d_in[9];
    const float* comp  = (const float*)d_in[10];
    const float* Wself = (const float*)d_in[11];
    const float* brg   = (const float*)d_in[12];
    const float* Wq    = (const float*)d_in[13];
    const float* Wk    = (const float*)d_in[14];
    const float* Wv    = (const float*)d_in[15];
    const float* Wo    = (const float*)d_in[16];
    const float* rvecs = (const float*)d_in[17];
    const float* Wfuse = (const float*)d_in[18];
    const float* bfuse = (const float*)d_in[19];
    const float* Wout  = (const float*)d_in[20];
    const float* bout  = (const float*)d_in[21];
    float* out = (float*)d_out;

    // Fused projections: hidden(self)+bias, P0, P1, Q, K, V
    gemm6_kernel<<<dim3(5, 8, 6), 512>>>(utt, Wself, brg, Wb, Wq, Wk, Wv);

    // RGCN edge scatter (uses hidden, P0, P1)
    scatter_kernel<<<EN, 128>>>(ssrc, sdst, setyp, comp);

    // Windowed attention path
    attn_ctx_kernel<<<LN, 128>>>();
    gemmWo_kernel<<<dim3(5, 8, 1), 512>>>(Wo);

    // Concept graph attention (dominant gather; norm folded in)
    concept_kernel<<<dim3(SN, LN, 3), 256>>>(csrc, cdst, cwgt, csen, table, rvecs);

    // Node attention + fusion head
    symfeat_kernel<<<LN, 128>>>();
    gemmFuse_kernel<<<dim3(5, 8, 1), 512>>>(Wfuse, bfuse);
    head_kernel<<<LN / 8, 256>>>(Wout, bout, out);
}

// round 7
// speedup vs baseline: 1.1688x; 1.1688x over previous
#include <cuda_runtime.h>
#include <math.h>

// Problem constants
constexpr int LN = 256;    // utterances
constexpr int DN = 300;    // embedding dim
constexpr int SN = 16;     // concepts per utterance
constexpr int KN = 16;     // dst per concept
constexpr int EN = 2048;   // edges
constexpr int CN = 7;      // classes
constexpr float NEGV = -1000000000.0f;

// Scratch (device globals, no allocation)
__device__ float g_hidden[LN * DN];
__device__ float g_P0[LN * DN];   // utt @ W_basis[0]
__device__ float g_P1[LN * DN];   // utt @ W_basis[1]
__device__ float g_Q[LN * DN];
__device__ float g_K[LN * DN];
__device__ float g_V[LN * DN];
__device__ float g_ctx[LN * DN];
__device__ float g_relatt[LN * DN];
__device__ float g_nodes[(long)LN * 48 * DN]; // 14.7 MB
__device__ float g_score[LN * 48];
__device__ int   g_nmask[LN * 48];
__device__ float g_feat[LN * 900];
__device__ float g_fuse[LN * DN];

// ---------------------------------------------------------------------------
// Tiled SGEMM: O[16x64 tile] = A[.. x Kdim] @ W[Kdim x 300]
// 256 threads, 1x4 micro-tile. Double-buffered K chunks of 32 w/ reg prefetch.
// A is pre-offset by koff (row stride lda); W pre-offset by koff*DN.
// atomic=true -> atomicAdd into O (split-K accumulation), no bias.
__device__ __forceinline__ void gemm_core(
    const float* __restrict__ A, int lda, const float* __restrict__ W,
    const float* __restrict__ bias, float* __restrict__ O,
    int Kdim, bool atomic)
{
    __shared__ float As[2][16][33];
    __shared__ __align__(16) float Ws[2][32][64];
    int t = threadIdx.x;               // 0..255
    int m0 = blockIdx.y * 16, n0 = blockIdx.x * 64;
    int row = t >> 4;                  // 0..15
    int col0 = (t & 15) * 4;           // 0..60
    int ar = t >> 5, ac = t & 31;      // A loader: rows ar, ar+8; col ac
    int wr = t >> 6, wc = t & 63;      // W loader: rows wr+4i; col wc
    float acc0 = 0.f, acc1 = 0.f, acc2 = 0.f, acc3 = 0.f;
    int nchunks = (Kdim + 31) >> 5;

    float a_reg[2], w_reg[8];
    a_reg[0] = (ac < Kdim) ? A[(m0 + ar) * lda + ac] : 0.f;
    a_reg[1] = (ac < Kdim) ? A[(m0 + ar + 8) * lda + ac] : 0.f;
#pragma unroll
    for (int i = 0; i < 8; i++) {
        int kk = wr + i * 4, nn = n0 + wc;
        w_reg[i] = (kk < Kdim && nn < DN) ? W[kk * DN + nn] : 0.f;
    }
    As[0][ar][ac] = a_reg[0];
    As[0][ar + 8][ac] = a_reg[1];
#pragma unroll
    for (int i = 0; i < 8; i++) Ws[0][wr + i * 4][wc] = w_reg[i];
    __syncthreads();

    for (int c = 1; c < nchunks; c++) {
        int k0 = c << 5;
        {
            int kk = k0 + ac;
            a_reg[0] = (kk < Kdim) ? A[(m0 + ar) * lda + kk] : 0.f;
            a_reg[1] = (kk < Kdim) ? A[(m0 + ar + 8) * lda + kk] : 0.f;
        }
#pragma unroll
        for (int i = 0; i < 8; i++) {
            int kk = k0 + wr + i * 4, nn = n0 + wc;
            w_reg[i] = (kk < Kdim && nn < DN) ? W[kk * DN + nn] : 0.f;
        }
        int cur = (c - 1) & 1;
#pragma unroll
        for (int k = 0; k < 32; k++) {
            float4 w4 = *(const float4*)&Ws[cur][k][col0];
            float a = As[cur][row][k];
            acc0 += a * w4.x; acc1 += a * w4.y;
            acc2 += a * w4.z; acc3 += a * w4.w;
        }
        __syncthreads();
        int nxt = c & 1;
        As[nxt][ar][ac] = a_reg[0];
        As[nxt][ar + 8][ac] = a_reg[1];
#pragma unroll
        for (int i = 0; i < 8; i++) Ws[nxt][wr + i * 4][wc] = w_reg[i];
        __syncthreads();
    }
    int cur = (nchunks - 1) & 1;
#pragma unroll
    for (int k = 0; k < 32; k++) {
        float4 w4 = *(const float4*)&Ws[cur][k][col0];
        float a = As[cur][row][k];
        acc0 += a * w4.x; acc1 += a * w4.y;
        acc2 += a * w4.z; acc3 += a * w4.w;
    }

    int m = m0 + row;
    float vv[4] = { acc0, acc1, acc2, acc3 };
#pragma unroll
    for (int j = 0; j < 4; j++) {
        int n = n0 + col0 + j;
        if (n < DN) {
            if (atomic) {
                atomicAdd(&O[m * DN + n], vv[j]);
            } else {
                O[m * DN + n] = vv[j] + (bias ? bias[n] : 0.f);
            }
        }
    }
}

// Batched: z selects which of 6 projections of utt we compute.
__global__ void __launch_bounds__(256) gemm6_kernel(
    const float* __restrict__ utt,
    const float* __restrict__ Wself, const float* __restrict__ brg,
    const float* __restrict__ Wb,
    const float* __restrict__ Wq, const float* __restrict__ Wk2,
    const float* __restrict__ Wv)
{
    int z = blockIdx.z;
    const float* Wz;
    float* Oz;
    const float* bz = nullptr;
    switch (z) {
        case 0: Wz = Wself; Oz = g_hidden; bz = brg; break;
        case 1: Wz = Wb;            Oz = g_P0; break;
        case 2: Wz = Wb + DN * DN;  Oz = g_P1; break;
        case 3: Wz = Wq;  Oz = g_Q; break;
        case 4: Wz = Wk2; Oz = g_K; break;
        default: Wz = Wv; Oz = g_V; break;
    }
    gemm_core(utt, DN, Wz, bz, Oz, DN, false);
}

// relatt = ctx @ Wo
__global__ void __launch_bounds__(256) gemmWo_kernel(const float* __restrict__ Wo)
{
    gemm_core(g_ctx, DN, Wo, nullptr, g_relatt, DN, false);
}

// fuse += feat[:, z*300:(z+1)*300] @ Wfuse[z*300:(z+1)*300, :]  (split-K, atomic)
__global__ void __launch_bounds__(256) gemmFuse_kernel(const float* __restrict__ Wf)
{
    int koff = blockIdx.z * 300;
    gemm_core(g_feat + koff, 900, Wf + (long)koff * DN, nullptr, g_fuse, 300, true);
}

// ---------------------------------------------------------------------------
// RGCN edge scatter: hidden[dst] += comp[et,0]*P0[src] + comp[et,1]*P1[src]
__global__ void __launch_bounds__(128) scatter_kernel(
    const int* __restrict__ src, const int* __restrict__ dst,
    const int* __restrict__ et, const float* __restrict__ comp)
{
    int e = blockIdx.x;
    int sl = src[e], dl = dst[e], r = et[e];
    float c0 = comp[2 * r], c1 = comp[2 * r + 1];
    const float* p0 = g_P0 + (long)sl * DN;
    const float* p1 = g_P1 + (long)sl * DN;
    float* h = g_hidden + (long)dl * DN;
    for (int d = threadIdx.x; d < DN; d += blockDim.x)
        atomicAdd(h + d, c0 * p0[d] + c1 * p1[d]);
}

// ---------------------------------------------------------------------------
// Windowed attention context (only center q needed): ctx[l] = sum_j a[h,j]*V[win_j]
__global__ void __launch_bounds__(128) attn_ctx_kernel() {
    int l = blockIdx.x;
    int tid = threadIdx.x, warp = tid >> 5, lane = tid & 31;
    __shared__ float qsm[DN];
    __shared__ float lg[2][3];
    int w[3];
    w[0] = l > 0 ? l - 1 : 0;
    w[1] = l;
    w[2] = l < LN - 1 ? l + 1 : LN - 1;
    for (int d = tid; d < DN; d += blockDim.x) qsm[d] = g_Q[l * DN + d];
    __syncthreads();
    for (int p = warp; p < 6; p += 4) {
        int h = p / 3, j = p - 3 * h;
        const float* kr = g_K + (long)w[j] * DN + h * 150;
        const float* qh = qsm + h * 150;
        float acc = 0.f;
        for (int d = lane; d < 150; d += 32) acc += qh[d] * kr[d];
        for (int off = 16; off; off >>= 1) acc += __shfl_down_sync(0xffffffffu, acc, off);
        if (lane == 0) lg[h][j] = acc * 0.081649658092772603f;  // 1/sqrt(150)
    }
    __syncthreads();
    float a[2][3];
#pragma unroll
    for (int h = 0; h < 2; h++) {
        float m = fmaxf(lg[h][0], fmaxf(lg[h][1], lg[h][2]));
        float s = 0.f;
#pragma unroll
        for (int j = 0; j < 3; j++) { a[h][j] = expf(lg[h][j] - m); s += a[h][j]; }
        float inv = 1.f / s;
#pragma unroll
        for (int j = 0; j < 3; j++) a[h][j] *= inv;
    }
    for (int d = tid; d < DN; d += blockDim.x) {
        int h = d >= 150;
        float c = a[h][0] * g_V[(long)w[0] * DN + d]
                + a[h][1] * g_V[(long)w[1] * DN + d]
                + a[h][2] * g_V[(long)w[2] * DN + d];
        g_ctx[l * DN + d] = c;
    }
}

// ---------------------------------------------------------------------------
// Concept two-level attention. One block per (n,l,s), 256 threads (8 warps).
// Gathered rows cached in SMEM (float4) and read from global exactly once.
__global__ void __launch_bounds__(256) concept_kernel(
    const int* __restrict__ src_ids, const int* __restrict__ dst_ids,
    const float* __restrict__ wgt, const float* __restrict__ sen,
    const float* __restrict__ table, const float* __restrict__ rvecs)
{
    int s = blockIdx.x, l = blockIdx.y, n = blockIdx.z;
    int tid = threadIdx.x, warp = tid >> 5, lane = tid & 31;
    __shared__ __align__(16) float4 dstc4[KN][75];
    __shared__ __align__(16) float4 srcsm4[75], rsm4[75], relsm4[75], sr4[75];
    __shared__ float d_du[KN], d_nn[KN], d_dp[KN];
    __shared__ int d_val[KN];
    __shared__ float red[8];
    __shared__ float s_nrm;

    int sidx = (n * LN + l) * SN + s;
    int src_id = src_ids[sidx];
    const float4* srow4 = (const float4*)(table + (long)(src_id < 0 ? 0 : src_id) * DN);
    const float4* rel4 = (const float4*)(g_relatt + (long)l * DN);
    const float4* rv4 = (const float4*)(rvecs + (long)n * DN);
    if (tid == 0) s_nrm = 0.f;
    __syncthreads();
    if (tid < 75) {
        float4 v = rel4[tid];
        relsm4[tid] = v;
        atomicAdd(&s_nrm, v.x * v.x + v.y * v.y + v.z * v.z + v.w * v.w);
    } else if (tid < 150) {
        rsm4[tid - 75] = rv4[tid - 75];
    } else if (tid < 225) {
        srcsm4[tid - 150] = srow4[tid - 150];
    }
    __syncthreads();
    if (tid < 75) {
        float4 sv = srcsm4[tid], rv = rsm4[tid];
        sr4[tid] = make_float4(sv.x * rv.x, sv.y * rv.y, sv.z * rv.z, sv.w * rv.w);
    }
    __syncthreads();

    long base = (long)sidx * KN;
#pragma unroll
    for (int kk = 0; kk < 2; kk++) {
        int k = warp + kk * 8;
        int id = dst_ids[base + k];
        const float4* rowv = (const float4*)(table + (long)(id < 0 ? 0 : id) * DN);
        float du = 0.f, nn = 0.f, dp = 0.f;
        for (int i = lane; i < 75; i += 32) {
            float4 v = rowv[i];
            dstc4[k][i] = v;
            float4 rl = relsm4[i];
            float4 sv = sr4[i];
            du += rl.x * v.x + rl.y * v.y + rl.z * v.z + rl.w * v.w;
            nn += v.x * v.x + v.y * v.y + v.z * v.z + v.w * v.w;
            dp += sv.x * v.x + sv.y * v.y + sv.z * v.z + sv.w * v.w;
        }
        for (int off = 16; off; off >>= 1) {
            du += __shfl_down_sync(0xffffffffu, du, off);
            nn += __shfl_down_sync(0xffffffffu, nn, off);
            dp += __shfl_down_sync(0xffffffffu, dp, off);
        }
        if (lane == 0) { d_du[k] = du; d_nn[k] = nn; d_dp[k] = dp; d_val[k] = (id >= 0); }
    }
    __syncthreads();

    // Tiny softmaxes, redundantly per active thread (only tid<75 need them).
    float ssc = 0.f;
    if (tid < 75) {
        float rn = sqrtf(s_nrm);
        float a1[KN], w2[KN];
        {
            float om[KN];
            float mx = NEGV;
#pragma unroll
            for (int k = 0; k < KN; k++) {
                if (d_val[k]) {
                    float cosv = fabsf(d_du[k]) / (rn * sqrtf(d_nn[k]) + 1e-8f);
                    om[k] = 0.5f * wgt[base + k] * cosv + 0.5f * fabsf(sen[base + k]);
                } else om[k] = NEGV;
                mx = fmaxf(mx, om[k]);
            }
            float sum = 0.f;
#pragma unroll
            for (int k = 0; k < KN; k++) { a1[k] = expf(om[k] - mx); sum += a1[k]; }
            float inv = 1.f / sum;
#pragma unroll
            for (int k = 0; k < KN; k++) a1[k] = a1[k] * inv * (d_val[k] ? 1.f : 0.f);

            float sk[KN], a2[KN];
            mx = NEGV;
#pragma unroll
            for (int k = 0; k < KN; k++) {
                sk[k] = d_val[k] ? a1[k] * d_dp[k] : NEGV;
                mx = fmaxf(mx, sk[k]);
            }
            sum = 0.f;
#pragma unroll
            for (int k = 0; k < KN; k++) { a2[k] = expf(sk[k] - mx); sum += a2[k]; }
            inv = 1.f / sum;
#pragma unroll
            for (int k = 0; k < KN; k++) w2[k] = a2[k] * inv * (d_val[k] ? 1.f : 0.f) * a1[k];
        }

        // src2 (float4) and its score against relatt
        float4 a = make_float4(0.f, 0.f, 0.f, 0.f);
#pragma unroll
        for (int k = 0; k < KN; k++) {
            float4 dv = dstc4[k][tid];
            a.x += w2[k] * dv.x; a.y += w2[k] * dv.y;
            a.z += w2[k] * dv.z; a.w += w2[k] * dv.w;
        }
        float4 sv = srcsm4[tid];
        float4 rv = rsm4[tid];
        float4 v;
        v.x = sv.x + rv.x * a.x; v.y = sv.y + rv.y * a.y;
        v.z = sv.z + rv.z * a.z; v.w = sv.w + rv.w * a.w;
        long nbase = ((long)l * 48 + n * SN + s) * 75;
        ((float4*)g_nodes)[nbase + tid] = v;
        float4 rl = relsm4[tid];
        ssc = rl.x * v.x + rl.y * v.y + rl.z * v.z + rl.w * v.w;
    }
    for (int off = 16; off; off >>= 1) ssc += __shfl_down_sync(0xffffffffu, ssc, off);
    if (lane == 0) red[warp] = ssc;
    __syncthreads();
    if (tid == 0) {
        g_score[l * 48 + n * SN + s] = red[0] + red[1] + red[2];
        g_nmask[l * 48 + n * SN + s] = (src_id >= 0);
    }
}

// ---------------------------------------------------------------------------
// Node-level attention -> sym; assemble feat = [hidden | relatt | sym] (float4)
// Also zeroes g_fuse (split-K accumulator) for this row.
__global__ void __launch_bounds__(128) symfeat_kernel() {
    int l = blockIdx.x;
    int tid = threadIdx.x;
    __shared__ float att[48];
    __shared__ float scs[48];
    __shared__ int msk[48];
    __shared__ float anyf;
    if (tid < 48) {
        msk[tid] = g_nmask[l * 48 + tid];
        scs[tid] = g_score[l * 48 + tid];
    }
    __syncthreads();
    if (tid == 0) {
        float v[48];
        float mx = NEGV;
        int any = 0;
        for (int j = 0; j < 48; j++) {
            v[j] = msk[j] ? scs[j] : NEGV;
            mx = fmaxf(mx, v[j]);
            any |= msk[j];
        }
        float sum = 0.f;
        for (int j = 0; j < 48; j++) { v[j] = expf(v[j] - mx); sum += v[j]; }
        float inv = 1.f / sum;
        for (int j = 0; j < 48; j++) att[j] = v[j] * inv * (msk[j] ? 1.f : 0.f);
        anyf = any ? 1.f : 0.f;
    }
    __syncthreads();
    if (tid < 75) {
        const float4* nodes4 = (const float4*)g_nodes;
        float4 acc = make_float4(0.f, 0.f, 0.f, 0.f);
#pragma unroll 8
        for (int j = 0; j < 48; j++) {
            float4 v = nodes4[((long)l * 48 + j) * 75 + tid];
            float a = att[j];
            acc.x += a * v.x; acc.y += a * v.y; acc.z += a * v.z; acc.w += a * v.w;
        }
        float an = anyf;
        acc.x *= an; acc.y *= an; acc.z *= an; acc.w *= an;
        float4* feat4 = (float4*)g_feat;
        const float4* hid4 = (const float4*)g_hidden;
        const float4* rel4 = (const float4*)g_relatt;
        feat4[(long)l * 225 + tid] = hid4[(long)l * 75 + tid];
        feat4[(long)l * 225 + 75 + tid] = rel4[(long)l * 75 + tid];
        feat4[(long)l * 225 + 150 + tid] = acc;
        // zero split-K accumulator
        ((float4*)g_fuse)[(long)l * 75 + tid] = make_float4(0.f, 0.f, 0.f, 0.f);
    }
}

// ---------------------------------------------------------------------------
// head: out[l] = log_softmax(relu(fuse[l]+bfuse) @ W_out + b_out). One warp/row.
__global__ void __launch_bounds__(256) head_kernel(
    const float* __restrict__ bf,
    const float* __restrict__ Wo2, const float* __restrict__ bo,
    float* __restrict__ out)
{
    int l = blockIdx.x * 8 + (threadIdx.x >> 5);
    int lane = threadIdx.x & 31;
    float acc[CN];
#pragma unroll
    for (int c = 0; c < CN; c++) acc[c] = 0.f;
    const float* hrow = g_fuse + (long)l * DN;
    for (int i = lane; i < DN; i += 32) {
        float h = fmaxf(hrow[i] + bf[i], 0.f);
#pragma unroll
        for (int c = 0; c < CN; c++) acc[c] += h * Wo2[i * CN + c];
    }
#pragma unroll
    for (int c = 0; c < CN; c++)
        for (int off = 16; off; off >>= 1)
            acc[c] += __shfl_down_sync(0xffffffffu, acc[c], off);
    if (lane == 0) {
        float lg[CN];
        float mx = NEGV;
#pragma unroll
        for (int c = 0; c < CN; c++) { lg[c] = acc[c] + bo[c]; mx = fmaxf(mx, lg[c]); }
        float sum = 0.f;
#pragma unroll
        for (int c = 0; c < CN; c++) sum += expf(lg[c] - mx);
        float ls = logf(sum) + mx;
#pragma unroll
        for (int c = 0; c < CN; c++) out[l * CN + c] = lg[c] - ls;
    }
}

// ---------------------------------------------------------------------------
extern "C" void kernel_launch(void* const* d_in, const int* in_sizes, int n_in,
                              void* d_out, int out_size)
{
    const float* utt   = (const float*)d_in[0];
    const int*   ssrc  = (const int*)d_in[1];
    const int*   sdst  = (const int*)d_in[2];
    const int*   setyp = (const int*)d_in[3];
    const int*   csrc  = (const int*)d_in[4];
    const int*   cdst  = (const int*)d_in[5];
    const float* cwgt  = (const float*)d_in[6];
    const float* csen  = (const float*)d_in[7];
    const float* table = (const float*)d_in[8];
    const float* Wb    = (const float*)d_in[9];
    const float* comp  = (const float*)d_in[10];
    const float* Wself = (const float*)d_in[11];
    const float* brg   = (const float*)d_in[12];
    const float* Wq    = (const float*)d_in[13];
    const float* Wk    = (const float*)d_in[14];
    const float* Wv    = (const float*)d_in[15];
    const float* Wo    = (const float*)d_in[16];
    const float* rvecs = (const float*)d_in[17];
    const float* Wfuse = (const float*)d_in[18];
    const float* bfuse = (const float*)d_in[19];
    const float* Wout  = (const float*)d_in[20];
    const float* bout  = (const float*)d_in[21];
    float* out = (float*)d_out;

    // Fused projections: hidden(self)+bias, P0, P1, Q, K, V  (16-row tiles)
    gemm6_kernel<<<dim3(5, 16, 6), 256>>>(utt, Wself, brg, Wb, Wq, Wk, Wv);

    // RGCN edge scatter (uses hidden, P0, P1)
    scatter_kernel<<<EN, 128>>>(ssrc, sdst, setyp, comp);

    // Windowed attention path
    attn_ctx_kernel<<<LN, 128>>>();
    gemmWo_kernel<<<dim3(5, 16, 1), 256>>>(Wo);

    // Concept graph attention (dominant gather; norm folded in)
    concept_kernel<<<dim3(SN, LN, 3), 256>>>(csrc, cdst, cwgt, csen, table, rvecs);

    // Node attention + feat assembly (+ zero split-K accumulator)
    symfeat_kernel<<<LN, 128>>>();

    // Fusion GEMM: split-K x3, atomic accumulate; bias+relu folded into head
    gemmFuse_kernel<<<dim3(5, 16, 3), 256>>>(Wfuse);
    head_kernel<<<LN / 8, 256>>>(bfuse, Wout, bout, out);
}